// round 1
// baseline (speedup 1.0000x reference)
#include <cuda_runtime.h>

// ---------------- problem constants ----------------
#define N_NODES 20000
#define E_EDGES 640000
#define H_DIM   128
#define U_DIM   128
#define K0PAD   264      // 259 (2H+V) padded to multiple of 8 for the k-paired GEMM
#define TE      64       // edges (or nodes) per block

// ---------------- device scratch (no allocs allowed) ----------------
__device__ float g_W0T [128 * 264];   // phi_e_w0^T, k-padded
__device__ float g_W1T [128 * 128];
__device__ float g_Wx0T[128 * 128];
__device__ float g_Wx1T[128 * 128];
__device__ float g_Wh0T[128 * 256];
__device__ float g_Wh1T[128 * 128];
__device__ float g_Wh2T[128 * 128];
__device__ float g_WoutT[3 * 128];
__device__ float g_mAcc[N_NODES * 128]; // segment-sum of m_ij * gate
__device__ float g_vAcc[N_NODES * 9];   // segment-sum of shifts

// ---------------- packed f32x2 helpers ----------------
__device__ __forceinline__ unsigned long long fma2(unsigned long long a,
                                                   unsigned long long b,
                                                   unsigned long long c) {
    unsigned long long d;
    asm("fma.rn.f32x2 %0, %1, %2, %3;" : "=l"(d) : "l"(a), "l"(b), "l"(c));
    return d;
}
__device__ __forceinline__ float hadd2(unsigned long long a) {
    float lo, hi;
    asm("mov.b64 {%0,%1}, %2;" : "=f"(lo), "=f"(hi) : "l"(a));
    return lo + hi;
}
__device__ __forceinline__ void red_add_v4(float* p, float x, float y, float z, float w) {
    asm volatile("red.global.add.v4.f32 [%0], {%1,%2,%3,%4};"
                 :: "l"(p), "f"(x), "f"(y), "f"(z), "f"(w) : "memory");
}
__device__ __forceinline__ float silu(float v) {
    return v * (1.0f / (1.0f + __expf(-v)));
}

// ---------------- 64xK @ KT x128 GEMM, f32x2 along K ----------------
// sIn : [64][inStride] fp32, K columns valid (K multiple of 4, zero-padded)
// WT  : global, transposed weights [128][Kpad]
// sOut: [64][outStride], 128 output columns
// sW  : smem tile, 128*64 floats, chunk-rotated layout
// Thread map: lane -> output cols {lane, lane+32, lane+64, lane+96}
//             warp (tid>>5) -> 8 edge rows
__device__ __forceinline__ void gemm64(
    const float* sIn, int inStride,
    const float* __restrict__ WT, int Kpad, int K,
    const float* __restrict__ bias,
    float* sOut, int outStride, bool act,
    float* sW, int tid)
{
    const int lane = tid & 31;
    const int e0   = (tid >> 5) * 8;

    unsigned long long acc[8][4];
#pragma unroll
    for (int i = 0; i < 8; i++)
#pragma unroll
        for (int j = 0; j < 4; j++) acc[i][j] = 0ull;

    for (int k0 = 0; k0 < K; k0 += 64) {
        int kc = K - k0; if (kc > 64) kc = 64;
        const int n4 = kc >> 2;
        __syncthreads();   // protect sW reuse + make producer writes visible
        for (int idx = tid; idx < 128 * n4; idx += 256) {
            int o   = idx / n4;
            int kk4 = idx - o * n4;
            int pos = (kk4 + o) & 15;               // bank-rotation
            *(float4*)&sW[o * 64 + pos * 4] =
                *(const float4*)&WT[o * Kpad + k0 + kk4 * 4];
        }
        __syncthreads();
#pragma unroll 2
        for (int kk = 0; kk < kc; kk += 4) {
            const int kk4 = kk >> 2;
            ulonglong2 w[4];
#pragma unroll
            for (int j = 0; j < 4; j++) {
                int o   = lane + 32 * j;
                int pos = (kk4 + o) & 15;
                w[j] = *(const ulonglong2*)&sW[o * 64 + pos * 4];
            }
#pragma unroll
            for (int i = 0; i < 8; i++) {
                ulonglong2 x = *(const ulonglong2*)&sIn[(e0 + i) * inStride + k0 + kk];
#pragma unroll
                for (int j = 0; j < 4; j++) {
                    acc[i][j] = fma2(x.x, w[j].x, acc[i][j]);
                    acc[i][j] = fma2(x.y, w[j].y, acc[i][j]);
                }
            }
        }
    }

    float b[4];
#pragma unroll
    for (int j = 0; j < 4; j++) b[j] = bias[lane + 32 * j];
    __syncthreads();
#pragma unroll
    for (int i = 0; i < 8; i++) {
#pragma unroll
        for (int j = 0; j < 4; j++) {
            float v = hadd2(acc[i][j]) + b[j];
            if (act) v = silu(v);
            sOut[(e0 + i) * outStride + lane + 32 * j] = v;
        }
    }
}

// SMEM layout sizes (floats)
#define EDGE_SMEM_FLOATS (64*264 + 64*132 + 128*64 + 64*16 + 512 + 64 + 64)
#define NODE_SMEM_FLOATS (64*264 + 64*132 + 128*64)

// ---------------- edge kernel: fused phi_e / phi_x / phi_inf + scatters ----
extern "C" __global__ void __launch_bounds__(256, 1)
edge_kernel(const float* __restrict__ pos, const float* __restrict__ feat,
            const int* __restrict__ senders, const int* __restrict__ receivers,
            const float* __restrict__ b_e0, const float* __restrict__ b_e1,
            const float* __restrict__ b_x0, const float* __restrict__ b_x1,
            const float* __restrict__ b_xo, const float* __restrict__ w_inf,
            const float* __restrict__ b_inf)
{
    extern __shared__ float sm[];
    float* sX     = sm;                   // 64*264 (phi_e input, later aliased)
    float* sA     = sX + 64 * 264;        // 64*132 ping buffer
    float* sW     = sA + 64 * 132;        // 128*64 weight tile
    float* sVec   = sW + 128 * 64;        // 64*16: 9 vec comps + 3 lengths
    float* sSmall = sVec + 64 * 16;       // 384 WoutT + 128 winf
    float* sGate  = sSmall + 512;         // 64 gates
    int*   sRecv  = (int*)(sGate + 64);   // 64 receiver ids
    float* sM  = sX;                      // [64][132] alias (phi_e out)
    float* sP2 = sX + 64 * 132;           // [64][132] alias (phi_x torso out)

    const int tid   = threadIdx.x;
    const int eBase = blockIdx.x * TE;

    for (int i = tid; i < 384; i += 256) sSmall[i] = g_WoutT[i];
    for (int i = tid; i < 128; i += 256) sSmall[384 + i] = w_inf[i];

    // geometry per edge
    if (tid < 64) {
        const int e = eBase + tid;
        const int s = senders[e];
        const int r = receivers[e];
        sRecv[tid] = r;
        const float* ps = pos + s * 9;
        const float* pr = pos + r * 9;
#pragma unroll
        for (int v = 0; v < 3; v++) {
            float n2 = 0.f;
#pragma unroll
            for (int d = 0; d < 3; d++) {
                float dv = pr[v * 3 + d] - ps[v * 3 + d];
                sVec[tid * 16 + v * 3 + d] = dv;
                n2 += dv * dv;
            }
            sVec[tid * 16 + 9 + v] = (n2 > 0.f) ? sqrtf(n2) : 0.f;
            sX[tid * 264 + 256 + v] = n2;       // sq_lengths == n2
        }
#pragma unroll
        for (int k = 259; k < 264; k++) sX[tid * 264 + k] = 0.f;  // K padding
    }

    // feature gathers (all L2-resident)
    for (int idx = tid; idx < 64 * 64; idx += 256) {
        const int i = idx >> 6;
        const int q = idx & 63;
        const int e = eBase + i;
        if (q < 32) {
            const int s = senders[e];
            *(float4*)&sX[i * 264 + q * 4] = *(const float4*)&feat[s * 128 + q * 4];
        } else {
            const int r = receivers[e];
            *(float4*)&sX[i * 264 + 128 + (q - 32) * 4] =
                *(const float4*)&feat[r * 128 + (q - 32) * 4];
        }
    }
    __syncthreads();

    // phi_e (2 layers, silu) -> sM ; phi_x torso (2 layers, silu) -> sP2
    gemm64(sX, 264, g_W0T,  K0PAD, K0PAD, b_e0, sA,  132, true, sW, tid);
    gemm64(sA, 132, g_W1T,  128,   128,   b_e1, sM,  132, true, sW, tid);
    gemm64(sM, 132, g_Wx0T, 128,   128,   b_x0, sA,  132, true, sW, tid);
    gemm64(sA, 132, g_Wx1T, 128,   128,   b_x1, sP2, 132, true, sW, tid);
    __syncthreads();

    // phi_x final linear -> 3, shift scatter
    if (tid < 192) {
        const int i = tid / 3;
        const int v = tid - i * 3;
        const float* row = sP2 + i * 132;
        const float* wv  = sSmall + v * 128;
        float a0 = 0, a1 = 0, a2 = 0, a3 = 0;
#pragma unroll 8
        for (int k = 0; k < 128; k += 4) {
            a0 += row[k]     * wv[k];
            a1 += row[k + 1] * wv[k + 1];
            a2 += row[k + 2] * wv[k + 2];
            a3 += row[k + 3] * wv[k + 3];
        }
        const float phix = a0 + a1 + a2 + a3 + b_xo[v];
        const float len  = sVec[i * 16 + 9 + v];
        const float sc   = phix / (1.0f + len);
        const int   r    = sRecv[i];
#pragma unroll
        for (int d = 0; d < 3; d++)
            atomicAdd(&g_vAcc[r * 9 + v * 3 + d], sc * sVec[i * 16 + v * 3 + d]);
    }

    // phi_inf gate
    if (tid < 64) {
        const float* row = sM + tid * 132;
        const float* wv  = sSmall + 384;
        float a0 = 0, a1 = 0, a2 = 0, a3 = 0;
#pragma unroll 8
        for (int k = 0; k < 128; k += 4) {
            a0 += row[k]     * wv[k];
            a1 += row[k + 1] * wv[k + 1];
            a2 += row[k + 2] * wv[k + 2];
            a3 += row[k + 3] * wv[k + 3];
        }
        const float z = a0 + a1 + a2 + a3 + b_inf[0];
        sGate[tid] = 1.0f / (1.0f + __expf(-z));
    }
    __syncthreads();

    // m_i scatter: vectorized L2 reductions
    for (int idx = tid; idx < 64 * 32; idx += 256) {
        const int i = idx >> 5;
        const int c = (idx & 31) << 2;
        const float g = sGate[i];
        const float* row = sM + i * 132;
        const float4 m = *(const float4*)&row[c];
        red_add_v4(&g_mAcc[sRecv[i] * 128 + c], m.x * g, m.y * g, m.z * g, m.w * g);
    }
}

// ---------------- node kernel: phi_h + residuals + output ----------------
extern "C" __global__ void __launch_bounds__(256, 1)
node_kernel(const float* __restrict__ pos, const float* __restrict__ feat,
            const float* __restrict__ b_h0, const float* __restrict__ b_h1,
            const float* __restrict__ b_h2, float* __restrict__ out)
{
    extern __shared__ float sm[];
    float* sX  = sm;                 // 64*264
    float* sA  = sX + 64 * 264;      // 64*132
    float* sW  = sA + 64 * 132;      // 128*64
    float* sY2 = sX;                 // [64][132] alias after layer 1

    const int tid   = threadIdx.x;
    const int nBase = blockIdx.x * TE;
    const float invSq = 1.0f / sqrtf(19999.0f);

    for (int idx = tid; idx < 64 * 64; idx += 256) {
        const int i = idx >> 6;
        const int q = idx & 63;
        const int node = nBase + i;
        float4 v = make_float4(0.f, 0.f, 0.f, 0.f);
        if (node < N_NODES) {
            if (q < 32) {
                float4 m = *(const float4*)&g_mAcc[node * 128 + q * 4];
                v = make_float4(m.x * invSq, m.y * invSq, m.z * invSq, m.w * invSq);
            } else {
                v = *(const float4*)&feat[node * 128 + (q - 32) * 4];
            }
        }
        *(float4*)&sX[i * 264 + q * 4] = v;
    }
    for (int idx = tid; idx < 64 * 2; idx += 256) {
        const int i = idx >> 1;
        const int q = idx & 1;
        *(float4*)&sX[i * 264 + 256 + q * 4] = make_float4(0.f, 0.f, 0.f, 0.f);
    }
    __syncthreads();

    gemm64(sX,  264, g_Wh0T, 256, 256, b_h0, sA,  132, true,  sW, tid);
    gemm64(sA,  132, g_Wh1T, 128, 128, b_h1, sY2, 132, true,  sW, tid);
    gemm64(sY2, 132, g_Wh2T, 128, 128, b_h2, sA,  132, false, sW, tid);
    __syncthreads();

    // features_out = phi_h + residual
    for (int idx = tid; idx < 64 * 32; idx += 256) {
        const int i = idx >> 5;
        const int c = (idx & 31) << 2;
        const int node = nBase + i;
        if (node < N_NODES) {
            float4 h = *(const float4*)&sA[i * 132 + c];
            float4 f = *(const float4*)&feat[node * 128 + c];
            *(float4*)&out[(size_t)N_NODES * 9 + (size_t)node * 128 + c] =
                make_float4(h.x + f.x, h.y + f.y, h.z + f.z, h.w + f.w);
        }
    }
    // vectors_out = pos + shifts/(N-1)
    const float invNN = 1.0f / 19999.0f;
    for (int idx = tid; idx < 64 * 9; idx += 256) {
        const int i = idx / 9;
        const int c = idx - i * 9;
        const int node = nBase + i;
        if (node < N_NODES)
            out[node * 9 + c] = pos[node * 9 + c] + g_vAcc[node * 9 + c] * invNN;
    }
}

// ---------------- prep: transpose + pad weights ----------------
__global__ void prep_kernel(const float* __restrict__ w0, const float* __restrict__ w1,
                            const float* __restrict__ wx0, const float* __restrict__ wx1,
                            const float* __restrict__ wout,
                            const float* __restrict__ wh0, const float* __restrict__ wh1,
                            const float* __restrict__ wh2)
{
    const int idx    = blockIdx.x * blockDim.x + threadIdx.x;
    const int stride = gridDim.x * blockDim.x;
    for (int i = idx; i < 128 * 264; i += stride) {
        const int o = i / 264, k = i - o * 264;
        g_W0T[i] = (k < 259) ? w0[k * 128 + o] : 0.f;
    }
    for (int i = idx; i < 128 * 128; i += stride) {
        const int o = i >> 7, k = i & 127;
        g_W1T [i] = w1 [k * 128 + o];
        g_Wx0T[i] = wx0[k * 128 + o];
        g_Wx1T[i] = wx1[k * 128 + o];
        g_Wh1T[i] = wh1[k * 128 + o];
        g_Wh2T[i] = wh2[k * 128 + o];
    }
    for (int i = idx; i < 128 * 256; i += stride) {
        const int o = i >> 8, k = i & 255;
        g_Wh0T[i] = wh0[k * 128 + o];
    }
    for (int i = idx; i < 384; i += stride) {
        const int v = i >> 7, k = i & 127;
        g_WoutT[i] = wout[k * 3 + v];
    }
}

__global__ void zero_kernel()
{
    const int idx    = blockIdx.x * blockDim.x + threadIdx.x;
    const int stride = gridDim.x * blockDim.x;
    for (int i = idx; i < N_NODES * 128; i += stride) g_mAcc[i] = 0.f;
    for (int i = idx; i < N_NODES * 9;   i += stride) g_vAcc[i] = 0.f;
}

// ---------------- launch ----------------
extern "C" void kernel_launch(void* const* d_in, const int* in_sizes, int n_in,
                              void* d_out, int out_size)
{
    (void)in_sizes; (void)n_in; (void)out_size;
    const float* pos   = (const float*)d_in[0];
    const float* feat  = (const float*)d_in[1];
    const int* senders   = (const int*)d_in[2];
    const int* receivers = (const int*)d_in[3];
    const float* w_e0 = (const float*)d_in[4];  const float* b_e0 = (const float*)d_in[5];
    const float* w_e1 = (const float*)d_in[6];  const float* b_e1 = (const float*)d_in[7];
    const float* w_x0 = (const float*)d_in[8];  const float* b_x0 = (const float*)d_in[9];
    const float* w_x1 = (const float*)d_in[10]; const float* b_x1 = (const float*)d_in[11];
    const float* w_xo = (const float*)d_in[12]; const float* b_xo = (const float*)d_in[13];
    const float* w_if = (const float*)d_in[14]; const float* b_if = (const float*)d_in[15];
    const float* w_h0 = (const float*)d_in[16]; const float* b_h0 = (const float*)d_in[17];
    const float* w_h1 = (const float*)d_in[18]; const float* b_h1 = (const float*)d_in[19];
    const float* w_h2 = (const float*)d_in[20]; const float* b_h2 = (const float*)d_in[21];
    float* out = (float*)d_out;

    const size_t smemE = EDGE_SMEM_FLOATS * sizeof(float);
    const size_t smemN = NODE_SMEM_FLOATS * sizeof(float);
    cudaFuncSetAttribute(edge_kernel, cudaFuncAttributeMaxDynamicSharedMemorySize, (int)smemE);
    cudaFuncSetAttribute(node_kernel, cudaFuncAttributeMaxDynamicSharedMemorySize, (int)smemN);

    prep_kernel<<<128, 256>>>(w_e0, w_e1, w_x0, w_x1, w_xo, w_h0, w_h1, w_h2);
    zero_kernel<<<256, 256>>>();
    edge_kernel<<<E_EDGES / TE, 256, smemE>>>(pos, feat, senders, receivers,
                                              b_e0, b_e1, b_x0, b_x1, b_xo, w_if, b_if);
    node_kernel<<<(N_NODES + TE - 1) / TE, 256, smemN>>>(pos, feat, b_h0, b_h1, b_h2, out);
}